// round 1
// baseline (speedup 1.0000x reference)
#include <cuda_runtime.h>
#include <math.h>

// Problem constants
static constexpr int BATCH = 4;
static constexpr int SEQ   = 2048;
static constexpr int DIM   = 1024;   // D_IN == D_OUT == 1024

// SGEMM tiling
#define BM 128
#define BN 128
#define BK 8
#define TM 8
#define TN 8
#define NTHREADS 256   // (BM/TM)*(BN/TN)

// Scratch (device globals — allocation-free per harness rules)
__device__ float g_Q[(size_t)BATCH * SEQ * DIM];
__device__ float g_K[(size_t)BATCH * SEQ * DIM];
__device__ float g_V[(size_t)BATCH * SEQ * DIM];
__device__ float g_S[(size_t)BATCH * SEQ * SEQ];

// ---------------------------------------------------------------------------
// C[m,n] = alpha * sum_k A[m,k] * B[n,k]    (both operands K-major, "NT")
// Optional causal block skip: with BM==BN, a block is fully above the diagonal
// iff n0 > m0 (both multiples of 128) -> return without writing.
// ---------------------------------------------------------------------------
__global__ __launch_bounds__(NTHREADS) void sgemm_nt(
    const float* __restrict__ A, const float* __restrict__ B,
    float* __restrict__ C,
    int M, int Nn, int K, float alpha,
    size_t strideA, size_t strideB, size_t strideC,
    int causalSkip)
{
    const int bz = blockIdx.z;
    A += (size_t)bz * strideA;
    B += (size_t)bz * strideB;
    C += (size_t)bz * strideC;

    const int m0 = blockIdx.y * BM;
    const int n0 = blockIdx.x * BN;
    if (causalSkip && n0 > m0) return;

    __shared__ float As[BK][BM];
    __shared__ float Bs[BK][BN];

    const int tid  = threadIdx.x;
    const int trow = tid / (BN / TN);   // 0..15
    const int tcol = tid % (BN / TN);   // 0..15

    // Tile load mapping: 128 rows x 8 cols = 1024 floats = 256 x float4
    const int lRow = tid >> 1;          // 0..127
    const int lCol = (tid & 1) * 4;     // 0 or 4

    const float* aPtr = A + (size_t)(m0 + lRow) * K + lCol;
    const float* bPtr = B + (size_t)(n0 + lRow) * K + lCol;

    float acc[TM][TN];
    #pragma unroll
    for (int i = 0; i < TM; i++)
        #pragma unroll
        for (int j = 0; j < TN; j++) acc[i][j] = 0.f;

    for (int k0 = 0; k0 < K; k0 += BK) {
        float4 av = *reinterpret_cast<const float4*>(aPtr + k0);
        float4 bv = *reinterpret_cast<const float4*>(bPtr + k0);
        As[lCol + 0][lRow] = av.x; As[lCol + 1][lRow] = av.y;
        As[lCol + 2][lRow] = av.z; As[lCol + 3][lRow] = av.w;
        Bs[lCol + 0][lRow] = bv.x; Bs[lCol + 1][lRow] = bv.y;
        Bs[lCol + 2][lRow] = bv.z; Bs[lCol + 3][lRow] = bv.w;
        __syncthreads();

        #pragma unroll
        for (int k = 0; k < BK; k++) {
            float4 a0 = *reinterpret_cast<const float4*>(&As[k][trow * TM]);
            float4 a1 = *reinterpret_cast<const float4*>(&As[k][trow * TM + 4]);
            float4 b0 = *reinterpret_cast<const float4*>(&Bs[k][tcol * TN]);
            float4 b1 = *reinterpret_cast<const float4*>(&Bs[k][tcol * TN + 4]);
            float ra[TM] = {a0.x, a0.y, a0.z, a0.w, a1.x, a1.y, a1.z, a1.w};
            float rb[TN] = {b0.x, b0.y, b0.z, b0.w, b1.x, b1.y, b1.z, b1.w};
            #pragma unroll
            for (int i = 0; i < TM; i++)
                #pragma unroll
                for (int j = 0; j < TN; j++)
                    acc[i][j] = fmaf(ra[i], rb[j], acc[i][j]);
        }
        __syncthreads();
    }

    #pragma unroll
    for (int i = 0; i < TM; i++) {
        float* cRow = C + (size_t)(m0 + trow * TM + i) * Nn + n0 + tcol * TN;
        float4 o0, o1;
        o0.x = alpha * acc[i][0]; o0.y = alpha * acc[i][1];
        o0.z = alpha * acc[i][2]; o0.w = alpha * acc[i][3];
        o1.x = alpha * acc[i][4]; o1.y = alpha * acc[i][5];
        o1.z = alpha * acc[i][6]; o1.w = alpha * acc[i][7];
        *reinterpret_cast<float4*>(cRow)     = o0;
        *reinterpret_cast<float4*>(cRow + 4) = o1;
    }
}

// ---------------------------------------------------------------------------
// C[m,n] = sum_k A[m,k] * B[k,n]   ("NN": A row-major K-contig, B row-major N-contig)
// Optional causal K-limit: only k < m0 + BM contributes (P is zero beyond).
// ---------------------------------------------------------------------------
__global__ __launch_bounds__(NTHREADS) void sgemm_nn(
    const float* __restrict__ A, const float* __restrict__ B,
    float* __restrict__ C,
    int M, int Nn, int K,
    size_t strideA, size_t strideB, size_t strideC,
    int causalKLimit)
{
    const int bz = blockIdx.z;
    A += (size_t)bz * strideA;
    B += (size_t)bz * strideB;
    C += (size_t)bz * strideC;

    const int m0 = blockIdx.y * BM;
    const int n0 = blockIdx.x * BN;
    const int kEnd = causalKLimit ? min(K, m0 + BM) : K;

    __shared__ float As[BK][BM];
    __shared__ float Bs[BK][BN];

    const int tid  = threadIdx.x;
    const int trow = tid / (BN / TN);
    const int tcol = tid % (BN / TN);

    const int aRow = tid >> 1;
    const int aCol = (tid & 1) * 4;
    const int bRow = tid >> 5;          // 0..7
    const int bCol = (tid & 31) * 4;    // 0..124

    const float* aPtr = A + (size_t)(m0 + aRow) * K + aCol;
    const float* bPtr = B + (size_t)bRow * Nn + n0 + bCol;

    float acc[TM][TN];
    #pragma unroll
    for (int i = 0; i < TM; i++)
        #pragma unroll
        for (int j = 0; j < TN; j++) acc[i][j] = 0.f;

    for (int k0 = 0; k0 < kEnd; k0 += BK) {
        float4 av = *reinterpret_cast<const float4*>(aPtr + k0);
        float4 bv = *reinterpret_cast<const float4*>(bPtr + (size_t)k0 * Nn);
        As[aCol + 0][aRow] = av.x; As[aCol + 1][aRow] = av.y;
        As[aCol + 2][aRow] = av.z; As[aCol + 3][aRow] = av.w;
        *reinterpret_cast<float4*>(&Bs[bRow][bCol]) = bv;
        __syncthreads();

        #pragma unroll
        for (int k = 0; k < BK; k++) {
            float4 a0 = *reinterpret_cast<const float4*>(&As[k][trow * TM]);
            float4 a1 = *reinterpret_cast<const float4*>(&As[k][trow * TM + 4]);
            float4 b0 = *reinterpret_cast<const float4*>(&Bs[k][tcol * TN]);
            float4 b1 = *reinterpret_cast<const float4*>(&Bs[k][tcol * TN + 4]);
            float ra[TM] = {a0.x, a0.y, a0.z, a0.w, a1.x, a1.y, a1.z, a1.w};
            float rb[TN] = {b0.x, b0.y, b0.z, b0.w, b1.x, b1.y, b1.z, b1.w};
            #pragma unroll
            for (int i = 0; i < TM; i++)
                #pragma unroll
                for (int j = 0; j < TN; j++)
                    acc[i][j] = fmaf(ra[i], rb[j], acc[i][j]);
        }
        __syncthreads();
    }

    #pragma unroll
    for (int i = 0; i < TM; i++) {
        float* cRow = C + (size_t)(m0 + trow * TM + i) * Nn + n0 + tcol * TN;
        float4 o0 = {acc[i][0], acc[i][1], acc[i][2], acc[i][3]};
        float4 o1 = {acc[i][4], acc[i][5], acc[i][6], acc[i][7]};
        *reinterpret_cast<float4*>(cRow)     = o0;
        *reinterpret_cast<float4*>(cRow + 4) = o1;
    }
}

// ---------------------------------------------------------------------------
// Causal row softmax, in place. Row (b, i) has valid length i+1.
// Also zeroes entries [i+1, round_up(i+1,128)) so the PV GEMM can consume
// full 128-wide k-tiles without masking.
// ---------------------------------------------------------------------------
__global__ __launch_bounds__(256) void softmax_rows(float* __restrict__ S)
{
    const int i = blockIdx.x;
    const int b = blockIdx.y;
    float* s = S + ((size_t)b * SEQ + i) * SEQ;
    const int len = i + 1;
    const int tid = threadIdx.x;
    __shared__ float red[8];

    // --- max ---
    float m = -3.4e38f;
    for (int j = tid; j < len; j += 256) m = fmaxf(m, s[j]);
    #pragma unroll
    for (int o = 16; o > 0; o >>= 1) m = fmaxf(m, __shfl_xor_sync(0xffffffffu, m, o));
    if ((tid & 31) == 0) red[tid >> 5] = m;
    __syncthreads();
    if (tid < 8) {
        float v = red[tid];
        #pragma unroll
        for (int o = 4; o > 0; o >>= 1) v = fmaxf(v, __shfl_xor_sync(0xffu, v, o));
        red[tid] = v;
    }
    __syncthreads();
    m = red[0];
    __syncthreads();

    // --- exp + sum ---
    float sum = 0.f;
    for (int j = tid; j < len; j += 256) {
        float e = __expf(s[j] - m);
        s[j] = e;
        sum += e;
    }
    #pragma unroll
    for (int o = 16; o > 0; o >>= 1) sum += __shfl_xor_sync(0xffffffffu, sum, o);
    if ((tid & 31) == 0) red[tid >> 5] = sum;
    __syncthreads();
    if (tid < 8) {
        float v = red[tid];
        #pragma unroll
        for (int o = 4; o > 0; o >>= 1) v += __shfl_xor_sync(0xffu, v, o);
        red[tid] = v;
    }
    __syncthreads();
    const float inv = 1.0f / red[0];

    // --- normalize + zero-pad to 128 boundary ---
    for (int j = tid; j < len; j += 256) s[j] *= inv;
    const int padEnd = (len + 127) & ~127;
    for (int j = len + tid; j < padEnd; j += 256) s[j] = 0.f;
}

// ---------------------------------------------------------------------------
extern "C" void kernel_launch(void* const* d_in, const int* in_sizes, int n_in,
                              void* d_out, int out_size)
{
    const float* x  = (const float*)d_in[0];
    const float* Wq = (const float*)d_in[1];
    const float* Wk = (const float*)d_in[2];
    const float* Wv = (const float*)d_in[3];
    float* out = (float*)d_out;

    float *Q, *K, *V, *S;
    cudaGetSymbolAddress((void**)&Q, g_Q);
    cudaGetSymbolAddress((void**)&K, g_K);
    cudaGetSymbolAddress((void**)&V, g_V);
    cudaGetSymbolAddress((void**)&S, g_S);

    const int MQ = BATCH * SEQ;           // 8192 flattened rows for projections
    const float scale = 1.0f / 32.0f;     // 1/sqrt(1024)

    dim3 blk(NTHREADS);

    // 1) Q, K, V projections: [8192,1024] = x @ W^T
    dim3 gProj(DIM / BN, MQ / BM, 1);
    sgemm_nt<<<gProj, blk>>>(x, Wq, Q, MQ, DIM, DIM, 1.f, 0, 0, 0, 0);
    sgemm_nt<<<gProj, blk>>>(x, Wk, K, MQ, DIM, DIM, 1.f, 0, 0, 0, 0);
    sgemm_nt<<<gProj, blk>>>(x, Wv, V, MQ, DIM, DIM, 1.f, 0, 0, 0, 0);

    // 2) S = (Q K^T) * scale, lower-triangular blocks only
    dim3 gS(SEQ / BN, SEQ / BM, BATCH);
    sgemm_nt<<<gS, blk>>>(Q, K, S, SEQ, SEQ, DIM, scale,
                          (size_t)SEQ * DIM, (size_t)SEQ * DIM,
                          (size_t)SEQ * SEQ, 1);

    // 3) causal softmax rows (in place, zero-pads to 128-boundary)
    dim3 gSm(SEQ, BATCH);
    softmax_rows<<<gSm, 256>>>(S);

    // 4) O = P V with causal k-limit
    dim3 gO(DIM / BN, SEQ / BM, BATCH);
    sgemm_nn<<<gO, blk>>>(S, V, out, SEQ, DIM, SEQ,
                          (size_t)SEQ * SEQ, (size_t)SEQ * DIM,
                          (size_t)SEQ * DIM, 1);
}

// round 3
// speedup vs baseline: 2.3417x; 2.3417x over previous
#include <cuda_runtime.h>
#include <cuda_bf16.h>
#include <cstdint>
#include <math.h>

// Problem constants
static constexpr int BATCH = 4;
static constexpr int SEQ   = 2048;
static constexpr int DIM   = 1024;

// Scratch (device globals — allocation-free per harness rules)
__device__ float g_Q [(size_t)BATCH * SEQ * DIM];
__device__ float g_K [(size_t)BATCH * SEQ * DIM];
__device__ float g_Vt[(size_t)BATCH * DIM * SEQ];   // V transposed: [b][o][token]
__device__ float g_S [(size_t)BATCH * SEQ * SEQ];

// ---------------------------------------------------------------------------
// SMEM tile geometry: 128 rows x 32 bf16 cols, row stride 80 bytes (pad).
// Four tiles per stage (Ahi, Alo, Bhi, Blo), two stages.
// ---------------------------------------------------------------------------
static constexpr int ROW_B   = 80;                    // bytes per smem row
static constexpr int TILE_B  = 128 * ROW_B;           // 10240
static constexpr int STAGE_B = 4 * TILE_B;            // 40960
static constexpr int SMEM_BYTES = 2 * STAGE_B;        // 81920

__device__ __forceinline__ uint32_t smem_u32(const void* p) {
    uint32_t a;
    asm("{ .reg .u64 t; cvta.to.shared.u64 t, %1; cvt.u32.u64 %0, t; }"
        : "=r"(a) : "l"(p));
    return a;
}

__device__ __forceinline__ uint32_t lds32(uint32_t a) {
    uint32_t v;
    asm("ld.shared.b32 %0, [%1];" : "=r"(v) : "r"(a));
    return v;
}

__device__ __forceinline__ void mma16816(float* c, const uint32_t* a,
                                         uint32_t b0, uint32_t b1) {
    asm volatile(
        "mma.sync.aligned.m16n8k16.row.col.f32.bf16.bf16.f32 "
        "{%0,%1,%2,%3}, {%4,%5,%6,%7}, {%8,%9}, {%0,%1,%2,%3};"
        : "+f"(c[0]), "+f"(c[1]), "+f"(c[2]), "+f"(c[3])
        : "r"(a[0]), "r"(a[1]), "r"(a[2]), "r"(a[3]), "r"(b0), "r"(b1));
}

// ---------------------------------------------------------------------------
// C[m,n] = alpha * sum_k A[m,k] * B[n,k]   (both K-major, fp32 in / fp32 out)
// via bf16 split-precision mma.sync (hi*hi + hi*lo + lo*hi), fp32 accum.
// CSKIP: skip 128x128 blocks fully above the diagonal.
// KLIM:  only k < m0+128 contributes.
// TOUT:  write C transposed per batch: C[(b*DIM + n)*SEQ + token]
// ---------------------------------------------------------------------------
template<bool CSKIP, bool KLIM, bool TOUT>
__global__ __launch_bounds__(256) void gemm_split_mma(
    const float* __restrict__ A, const float* __restrict__ B, float* __restrict__ C,
    int K, int lda, int ldb, int ldc, float alpha,
    size_t sA, size_t sB, size_t sC)
{
    const int bz = blockIdx.z;
    A += (size_t)bz * sA;
    B += (size_t)bz * sB;
    C += (size_t)bz * sC;

    const int m0 = blockIdx.y * 128;
    const int n0 = blockIdx.x * 128;
    if (CSKIP && n0 > m0) return;
    const int kEnd = KLIM ? min(K, m0 + 128) : K;
    const int nChunks = kEnd >> 5;          // K chunks of 32

    extern __shared__ __align__(16) uint8_t dsmem[];
    const uint32_t sbase = smem_u32(dsmem);

    const int tid    = threadIdx.x;
    const int wid    = tid >> 5;
    const int lane   = tid & 31;
    const int warp_m = wid & 3;             // 0..3 -> 32-row slices
    const int warp_n = wid >> 2;            // 0..1 -> 64-col slices
    const int r      = lane >> 2;           // 0..7
    const int q      = lane & 3;            // 0..3

    // ---- accumulators: warp tile 32x64 = 2 mtiles x 8 ntiles x 4 floats ----
    float acc[2][8][4];
    #pragma unroll
    for (int t = 0; t < 2; t++)
        #pragma unroll
        for (int j = 0; j < 8; j++)
            #pragma unroll
            for (int e = 0; e < 4; e++) acc[t][j][e] = 0.f;

    // ---- helpers as lambdas ----
    auto load_stage = [&](int k0, float4* aS, float4* bS) {
        #pragma unroll
        for (int i = 0; i < 4; i++) {
            const int idx = i * 256 + tid;
            const int row = idx >> 3;
            const int c4  = idx & 7;
            aS[i] = *reinterpret_cast<const float4*>(
                        &A[(size_t)(m0 + row) * lda + k0 + c4 * 4]);
            bS[i] = *reinterpret_cast<const float4*>(
                        &B[(size_t)(n0 + row) * ldb + k0 + c4 * 4]);
        }
    };

    auto split_store = [&](uint32_t stageBase, const float4* aS, const float4* bS) {
        const uint32_t aHi = stageBase;
        const uint32_t aLo = stageBase + TILE_B;
        const uint32_t bHi = stageBase + 2 * TILE_B;
        const uint32_t bLo = stageBase + 3 * TILE_B;
        #pragma unroll
        for (int i = 0; i < 4; i++) {
            const int idx = i * 256 + tid;
            const int row = idx >> 3;
            const int c4  = idx & 7;
            const uint32_t off = (uint32_t)(row * ROW_B + c4 * 8);

            #pragma unroll
            for (int m = 0; m < 2; m++) {
                const float4 f = m == 0 ? aS[i] : bS[i];
                const uint32_t hiB = (m == 0 ? aHi : bHi) + off;
                const uint32_t loB = (m == 0 ? aLo : bLo) + off;
                __nv_bfloat162 h01 = __float22bfloat162_rn(make_float2(f.x, f.y));
                __nv_bfloat162 h23 = __float22bfloat162_rn(make_float2(f.z, f.w));
                float2 g01 = __bfloat1622float2(h01);
                float2 g23 = __bfloat1622float2(h23);
                __nv_bfloat162 l01 = __float22bfloat162_rn(
                    make_float2(f.x - g01.x, f.y - g01.y));
                __nv_bfloat162 l23 = __float22bfloat162_rn(
                    make_float2(f.z - g23.x, f.w - g23.y));
                asm volatile("st.shared.v2.b32 [%0], {%1,%2};"
                             :: "r"(hiB), "r"(*(uint32_t*)&h01), "r"(*(uint32_t*)&h23));
                asm volatile("st.shared.v2.b32 [%0], {%1,%2};"
                             :: "r"(loB), "r"(*(uint32_t*)&l01), "r"(*(uint32_t*)&l23));
            }
        }
    };

    auto compute = [&](uint32_t stageBase) {
        const uint32_t aHi = stageBase;
        const uint32_t aLo = stageBase + TILE_B;
        const uint32_t bHi = stageBase + 2 * TILE_B;
        const uint32_t bLo = stageBase + 3 * TILE_B;
        #pragma unroll
        for (int s = 0; s < 2; s++) {
            const int kb = s * 16;
            const uint32_t kc = (uint32_t)((kb + q * 2) * 2);   // byte col

            uint32_t ah[2][4], al[2][4];
            #pragma unroll
            for (int t = 0; t < 2; t++) {
                const uint32_t row0 = (uint32_t)((warp_m * 32 + t * 16 + r) * ROW_B);
                ah[t][0] = lds32(aHi + row0 + kc);
                ah[t][1] = lds32(aHi + row0 + 8 * ROW_B + kc);
                ah[t][2] = lds32(aHi + row0 + kc + 16);
                ah[t][3] = lds32(aHi + row0 + 8 * ROW_B + kc + 16);
                al[t][0] = lds32(aLo + row0 + kc);
                al[t][1] = lds32(aLo + row0 + 8 * ROW_B + kc);
                al[t][2] = lds32(aLo + row0 + kc + 16);
                al[t][3] = lds32(aLo + row0 + 8 * ROW_B + kc + 16);
            }
            #pragma unroll
            for (int j = 0; j < 8; j++) {
                const uint32_t nrow = (uint32_t)((warp_n * 64 + j * 8 + r) * ROW_B);
                const uint32_t bh0 = lds32(bHi + nrow + kc);
                const uint32_t bh1 = lds32(bHi + nrow + kc + 16);
                const uint32_t bl0 = lds32(bLo + nrow + kc);
                const uint32_t bl1 = lds32(bLo + nrow + kc + 16);
                #pragma unroll
                for (int t = 0; t < 2; t++) {
                    mma16816(acc[t][j], ah[t], bh0, bh1);
                    mma16816(acc[t][j], ah[t], bl0, bl1);
                    mma16816(acc[t][j], al[t], bh0, bh1);
                }
            }
        }
    };

    // ---- pipelined main loop ----
    float4 aS[4], bS[4];
    load_stage(0, aS, bS);
    split_store(sbase, aS, bS);
    __syncthreads();

    for (int c = 0; c < nChunks; c++) {
        const bool more = (c + 1) < nChunks;
        if (more) load_stage((c + 1) << 5, aS, bS);
        compute(sbase + (uint32_t)(c & 1) * STAGE_B);
        if (more) {
            split_store(sbase + (uint32_t)((c + 1) & 1) * STAGE_B, aS, bS);
            __syncthreads();
        }
    }

    // ---- epilogue ----
    if (!TOUT) {
        #pragma unroll
        for (int t = 0; t < 2; t++)
            #pragma unroll
            for (int j = 0; j < 8; j++) {
                const int row = m0 + warp_m * 32 + t * 16 + r;
                const int col = n0 + warp_n * 64 + j * 8 + q * 2;
                float2 lo = make_float2(acc[t][j][0] * alpha, acc[t][j][1] * alpha);
                float2 hi = make_float2(acc[t][j][2] * alpha, acc[t][j][3] * alpha);
                *reinterpret_cast<float2*>(&C[(size_t)row * ldc + col])       = lo;
                *reinterpret_cast<float2*>(&C[(size_t)(row + 8) * ldc + col]) = hi;
            }
    } else {
        const int b    = m0 / SEQ;
        const int tokb = m0 % SEQ;
        #pragma unroll
        for (int t = 0; t < 2; t++)
            #pragma unroll
            for (int j = 0; j < 8; j++) {
                const int n   = n0 + warp_n * 64 + j * 8 + q * 2;
                const int tok = tokb + warp_m * 32 + t * 16 + r;
                float* c0 = &C[((size_t)b * DIM + n) * SEQ + tok];
                float* c1 = &C[((size_t)b * DIM + n + 1) * SEQ + tok];
                c0[0] = acc[t][j][0];
                c1[0] = acc[t][j][1];
                c0[8] = acc[t][j][2];
                c1[8] = acc[t][j][3];
            }
    }
}

// ---------------------------------------------------------------------------
// Causal row softmax, in place; zero-pads [len, ceil128(len)).
// ---------------------------------------------------------------------------
__global__ __launch_bounds__(256) void softmax_rows(float* __restrict__ S)
{
    const int i = blockIdx.x;
    const int b = blockIdx.y;
    float* s = S + ((size_t)b * SEQ + i) * SEQ;
    const int len = i + 1;
    const int tid = threadIdx.x;
    __shared__ float red[8];

    float m = -3.4e38f;
    for (int j = tid; j < len; j += 256) m = fmaxf(m, s[j]);
    #pragma unroll
    for (int o = 16; o > 0; o >>= 1) m = fmaxf(m, __shfl_xor_sync(0xffffffffu, m, o));
    if ((tid & 31) == 0) red[tid >> 5] = m;
    __syncthreads();
    if (tid < 8) {
        float v = red[tid];
        #pragma unroll
        for (int o = 4; o > 0; o >>= 1) v = fmaxf(v, __shfl_xor_sync(0xffu, v, o));
        red[tid] = v;
    }
    __syncthreads();
    m = red[0];
    __syncthreads();

    float sum = 0.f;
    for (int j = tid; j < len; j += 256) {
        float e = __expf(s[j] - m);
        s[j] = e;
        sum += e;
    }
    #pragma unroll
    for (int o = 16; o > 0; o >>= 1) sum += __shfl_xor_sync(0xffffffffu, sum, o);
    if ((tid & 31) == 0) red[tid >> 5] = sum;
    __syncthreads();
    if (tid < 8) {
        float v = red[tid];
        #pragma unroll
        for (int o = 4; o > 0; o >>= 1) v += __shfl_xor_sync(0xffu, v, o);
        red[tid] = v;
    }
    __syncthreads();
    const float inv = 1.0f / red[0];

    for (int j = tid; j < len; j += 256) s[j] *= inv;
    const int padEnd = (len + 127) & ~127;
    for (int j = len + tid; j < padEnd; j += 256) s[j] = 0.f;
}

// ---------------------------------------------------------------------------
extern "C" void kernel_launch(void* const* d_in, const int* in_sizes, int n_in,
                              void* d_out, int out_size)
{
    const float* x  = (const float*)d_in[0];
    const float* Wq = (const float*)d_in[1];
    const float* Wk = (const float*)d_in[2];
    const float* Wv = (const float*)d_in[3];
    float* out = (float*)d_out;

    float *Q, *K, *Vt, *S;
    cudaGetSymbolAddress((void**)&Q,  g_Q);
    cudaGetSymbolAddress((void**)&K,  g_K);
    cudaGetSymbolAddress((void**)&Vt, g_Vt);
    cudaGetSymbolAddress((void**)&S,  g_S);

    cudaFuncSetAttribute(gemm_split_mma<false, false, false>,
                         cudaFuncAttributeMaxDynamicSharedMemorySize, SMEM_BYTES);
    cudaFuncSetAttribute(gemm_split_mma<false, false, true>,
                         cudaFuncAttributeMaxDynamicSharedMemorySize, SMEM_BYTES);
    cudaFuncSetAttribute(gemm_split_mma<true, false, false>,
                         cudaFuncAttributeMaxDynamicSharedMemorySize, SMEM_BYTES);
    cudaFuncSetAttribute(gemm_split_mma<false, true, false>,
                         cudaFuncAttributeMaxDynamicSharedMemorySize, SMEM_BYTES);

    const int MQ = BATCH * SEQ;            // 8192 tokens
    const float scale = 1.0f / 32.0f;      // 1/sqrt(1024)
    dim3 blk(256);

    // 1) projections (tokens flattened; M=8192, N=1024, K=1024)
    dim3 gProj(DIM / 128, MQ / 128, 1);
    gemm_split_mma<false, false, false><<<gProj, blk, SMEM_BYTES>>>(
        x, Wq, Q, DIM, DIM, DIM, DIM, 1.f, 0, 0, 0);
    gemm_split_mma<false, false, false><<<gProj, blk, SMEM_BYTES>>>(
        x, Wk, K, DIM, DIM, DIM, DIM, 1.f, 0, 0, 0);
    gemm_split_mma<false, false, true><<<gProj, blk, SMEM_BYTES>>>(
        x, Wv, Vt, DIM, DIM, DIM, DIM, 1.f, 0, 0, 0);   // writes V^T per batch

    // 2) scores S = (Q K^T) * scale, lower-triangular blocks only
    dim3 gS(SEQ / 128, SEQ / 128, BATCH);
    gemm_split_mma<true, false, false><<<gS, blk, SMEM_BYTES>>>(
        Q, K, S, DIM, DIM, DIM, SEQ, scale,
        (size_t)SEQ * DIM, (size_t)SEQ * DIM, (size_t)SEQ * SEQ);

    // 3) causal softmax (in place, pads rows to 128-boundary with zeros)
    dim3 gSm(SEQ, BATCH);
    softmax_rows<<<gSm, 256>>>(S);

    // 4) O = P V  == NT with B = V^T (K-major over tokens), causal k-limit
    dim3 gO(DIM / 128, SEQ / 128, BATCH);
    gemm_split_mma<false, true, false><<<gO, blk, SMEM_BYTES>>>(
        S, Vt, out, SEQ, SEQ, SEQ, DIM, 1.f,
        (size_t)SEQ * SEQ, (size_t)DIM * SEQ, (size_t)SEQ * DIM);
}